// round 5
// baseline (speedup 1.0000x reference)
#include <cuda_runtime.h>
#include <cstdint>

// Custom_RoPE: x (32, 8192, 128) fp32, cos/sin (8192, 128) fp32.
// out = x*cos + rotate_half(x)*sin ; obs_max/min over last dim.
// d_out layout: out[H*T*D] | obs_max[H*T] | obs_min[H*T].
//
// R4: cp.async-staged pipeline to decouple outstanding DRAM lines from
// register pressure / occupancy (R1 vs R2 showed both configs were pinned at
// ~192 lines/SM -> 5.8 TB/s supply-limited).
//  - warp = 4 rows at same t (heads h, h+8, h+16, h+24), 8 t-iterations
//  - 3-stage cp.async.cg pipeline into 48KB static smem
//  - each lane cp.asyncs exactly the 4x16B chunks it later LDS-reads:
//    per-thread groups, zero block/warp syncs
//  - cos/sin via direct LDG (L2-resident), out via __stcs (best from R2/R3)

#define RH 32
#define RT 8192
#define RD 128
#define IT 8
#define DEPTH 3
#define WPB 8

__device__ __forceinline__ void cp_async16(uint32_t saddr, const float* gptr) {
    asm volatile("cp.async.cg.shared.global [%0], [%1], 16;"
                 :: "r"(saddr), "l"(gptr));
}
__device__ __forceinline__ void cp_commit() {
    asm volatile("cp.async.commit_group;" ::: "memory");
}
template <int N>
__device__ __forceinline__ void cp_wait() {
    asm volatile("cp.async.wait_group %0;" :: "n"(N) : "memory");
}

__global__ __launch_bounds__(256, 4) void rope_kernel(
    const float* __restrict__ x,
    const float* __restrict__ cosp,
    const float* __restrict__ sinp,
    float* __restrict__ out,
    float* __restrict__ omax,
    float* __restrict__ omin)
{
    // [DEPTH][WPB][4 rows][RD floats] = 3*8*4*128*4B = 49152 B
    __shared__ __align__(16) float smem[DEPTH * WPB * 4 * RD];

    const unsigned FULL = 0xffffffffu;
    int wib  = threadIdx.x >> 5;
    int w    = blockIdx.x * WPB + wib;      // [0, 8*1024)
    int lane = threadIdx.x & 31;
    int ll   = lane & 15;
    int half = lane >> 4;

    int tg = w & 1023;                      // t-group
    int h  = w >> 10;                       // [0, 8)
    int t0 = tg * IT;

    int hA = h + half * 16;                 // this lane's two heads
    int hB = h + 8 + half * 16;

    const float* xA = x + ((size_t)hA * RT + t0) * RD;
    const float* xB = x + ((size_t)hB * RT + t0) * RD;
    float*       oA = out + ((size_t)hA * RT + t0) * RD;
    float*       oB = out + ((size_t)hB * RT + t0) * RD;
    const float* cP = cosp + (size_t)t0 * RD;
    const float* sP = sinp + (size_t)t0 * RD;

    // lane-owned smem chunk offsets (floats) within a (stage,warp) buffer
    int riA = half * 2, riB = half * 2 + 1;
    int cAlo = riA * RD + ll * 4;
    int cAhi = riA * RD + 64 + ll * 4;
    int cBlo = riB * RD + ll * 4;
    int cBhi = riB * RD + 64 + ll * 4;

    float* wbuf0 = smem + (size_t)wib * 4 * RD;          // stage 0 buffer
    const int STAGE_STRIDE = WPB * 4 * RD;               // floats per stage

    uint32_t sb0 = (uint32_t)__cvta_generic_to_shared(wbuf0);

    // ---- prologue: issue iters 0..DEPTH-1 ----
    #pragma unroll
    for (int i = 0; i < DEPTH; i++) {
        uint32_t sb = sb0 + (uint32_t)(i * STAGE_STRIDE) * 4u;
        const float* xAi = xA + i * RD;
        const float* xBi = xB + i * RD;
        cp_async16(sb + cAlo * 4, xAi + ll * 4);
        cp_async16(sb + cAhi * 4, xAi + 64 + ll * 4);
        cp_async16(sb + cBlo * 4, xBi + ll * 4);
        cp_async16(sb + cBhi * 4, xBi + 64 + ll * 4);
        cp_commit();
    }

    #pragma unroll
    for (int i = 0; i < IT; i++) {
        int s = i % DEPTH;
        float* sb = wbuf0 + s * STAGE_STRIDE;

        // start long-latency c/s loads before waiting on the stage
        const float* cbi = cP + i * RD;
        const float* sbi = sP + i * RD;
        float4 clo = *(const float4*)(cbi + ll * 4);
        float4 chi = *(const float4*)(cbi + 64 + ll * 4);
        float4 slo = *(const float4*)(sbi + ll * 4);
        float4 shi = *(const float4*)(sbi + 64 + ll * 4);

        if (i <= IT - 3)      cp_wait<2>();
        else if (i == IT - 2) cp_wait<1>();
        else                  cp_wait<0>();

        float4 xloA = *(const float4*)(sb + cAlo);
        float4 xhiA = *(const float4*)(sb + cAhi);
        float4 xloB = *(const float4*)(sb + cBlo);
        float4 xhiB = *(const float4*)(sb + cBhi);

        // ---- row A ----
        float4 oloA, ohiA;
        oloA.x = fmaf(-xhiA.x, slo.x, xloA.x * clo.x);
        oloA.y = fmaf(-xhiA.y, slo.y, xloA.y * clo.y);
        oloA.z = fmaf(-xhiA.z, slo.z, xloA.z * clo.z);
        oloA.w = fmaf(-xhiA.w, slo.w, xloA.w * clo.w);
        ohiA.x = fmaf( xloA.x, shi.x, xhiA.x * chi.x);
        ohiA.y = fmaf( xloA.y, shi.y, xhiA.y * chi.y);
        ohiA.z = fmaf( xloA.z, shi.z, xhiA.z * chi.z);
        ohiA.w = fmaf( xloA.w, shi.w, xhiA.w * chi.w);
        __stcs((float4*)(oA + i * RD) + ll, oloA);
        __stcs((float4*)(oA + i * RD + 64) + ll, ohiA);

        // ---- row B ----
        float4 oloB, ohiB;
        oloB.x = fmaf(-xhiB.x, slo.x, xloB.x * clo.x);
        oloB.y = fmaf(-xhiB.y, slo.y, xloB.y * clo.y);
        oloB.z = fmaf(-xhiB.z, slo.z, xloB.z * clo.z);
        oloB.w = fmaf(-xhiB.w, slo.w, xloB.w * clo.w);
        ohiB.x = fmaf( xloB.x, shi.x, xhiB.x * chi.x);
        ohiB.y = fmaf( xloB.y, shi.y, xhiB.y * chi.y);
        ohiB.z = fmaf( xloB.z, shi.z, xhiB.z * chi.z);
        ohiB.w = fmaf( xloB.w, shi.w, xhiB.w * chi.w);
        __stcs((float4*)(oB + i * RD) + ll, oloB);
        __stcs((float4*)(oB + i * RD + 64) + ll, ohiB);

        // refill this stage with iter i+DEPTH (lane re-writes only its own
        // chunks, which it has already consumed into registers)
        if (i + DEPTH < IT) {
            uint32_t sbw = sb0 + (uint32_t)(s * STAGE_STRIDE) * 4u;
            const float* xAi = xA + (i + DEPTH) * RD;
            const float* xBi = xB + (i + DEPTH) * RD;
            cp_async16(sbw + cAlo * 4, xAi + ll * 4);
            cp_async16(sbw + cAhi * 4, xAi + 64 + ll * 4);
            cp_async16(sbw + cBlo * 4, xBi + ll * 4);
            cp_async16(sbw + cBhi * 4, xBi + 64 + ll * 4);
            cp_commit();
        }

        // ---- per-row max/min over 16-lane halves ----
        float mxA = fmaxf(fmaxf(fmaxf(oloA.x, oloA.y), fmaxf(oloA.z, oloA.w)),
                          fmaxf(fmaxf(ohiA.x, ohiA.y), fmaxf(ohiA.z, ohiA.w)));
        float mnA = fminf(fminf(fminf(oloA.x, oloA.y), fminf(oloA.z, oloA.w)),
                          fminf(fminf(ohiA.x, ohiA.y), fminf(ohiA.z, ohiA.w)));
        float mxB = fmaxf(fmaxf(fmaxf(oloB.x, oloB.y), fmaxf(oloB.z, oloB.w)),
                          fmaxf(fmaxf(ohiB.x, ohiB.y), fmaxf(ohiB.z, ohiB.w)));
        float mnB = fminf(fminf(fminf(oloB.x, oloB.y), fminf(oloB.z, oloB.w)),
                          fminf(fminf(ohiB.x, ohiB.y), fminf(ohiB.z, ohiB.w)));
        #pragma unroll
        for (int off = 8; off > 0; off >>= 1) {
            mxA = fmaxf(mxA, __shfl_xor_sync(FULL, mxA, off));
            mnA = fminf(mnA, __shfl_xor_sync(FULL, mnA, off));
            mxB = fmaxf(mxB, __shfl_xor_sync(FULL, mxB, off));
            mnB = fminf(mnB, __shfl_xor_sync(FULL, mnB, off));
        }
        if (ll == 0) {
            size_t rowA = (size_t)hA * RT + t0 + i;
            size_t rowB = (size_t)hB * RT + t0 + i;
            omax[rowA] = mxA;
            omin[rowA] = mnA;
            omax[rowB] = mxB;
            omin[rowB] = mnB;
        }
    }
}

extern "C" void kernel_launch(void* const* d_in, const int* in_sizes, int n_in,
                              void* d_out, int out_size)
{
    // inputs: 0=x, 1=scale_x (unused), 2=cos, 3=scale_cos (unused),
    //         4=sin, 5=scale_sin (unused)
    const float* x    = (const float*)d_in[0];
    const float* cosp = (const float*)d_in[2];
    const float* sinp = (const float*)d_in[4];

    float* out  = (float*)d_out;
    float* omax = out + (size_t)RH * RT * RD;
    float* omin = omax + (size_t)RH * RT;

    const int warps  = 8 * (RT / IT);       // 8 h-slots * 1024 t-groups = 8192
    const int blocks = warps / WPB;         // 1024

    rope_kernel<<<blocks, WPB * 32>>>(x, cosp, sinp, out, omax, omin);
}

// round 6
// speedup vs baseline: 1.1300x; 1.1300x over previous
#include <cuda_runtime.h>

// Custom_RoPE: x (32, 8192, 128) fp32, cos/sin (8192, 128) fp32.
// out = x*cos + rotate_half(x)*sin ; obs_max/min over last dim.
// d_out layout: out[H*T*D] | obs_max[H*T] | obs_min[H*T].
//
// R5: exact R2 structure (best known: 39.1us kernel, 5.79 TB/s) with ONE
// change: output stores use __stwt (write-through, no L2 allocation).
// Output is never re-read; keeping it out of L2 entirely removes dirty-line
// churn against the streaming read path and protects cos/sin residency.
//  - warp = 4 rows at same t (heads h, h+8, h+16, h+24)
//  - lanes 0-15 -> heads {h, h+8}; lanes 16-31 -> {h+16, h+24}
//  - one cos/sin load serves 4 rows; zero-shuffle rotate
//  - __ldcs on x (streaming reads), 16-lane butterflies for max/min

#define RH 32
#define RT 8192
#define RD 128

__global__ __launch_bounds__(256, 4) void rope_kernel(
    const float* __restrict__ x,
    const float* __restrict__ cosp,
    const float* __restrict__ sinp,
    float* __restrict__ out,
    float* __restrict__ omax,
    float* __restrict__ omin)
{
    const unsigned FULL = 0xffffffffu;
    int w    = (blockIdx.x * blockDim.x + threadIdx.x) >> 5;  // [0, 8*T)
    int lane = threadIdx.x & 31;
    int ll   = lane & 15;          // lane within half-warp
    int half = lane >> 4;          // head offset 0 or 16

    int t = w & (RT - 1);
    int h = w >> 13;               // [0, 8)

    size_t rowA = (size_t)(h     + half * 16) * RT + t;   // head h   / h+16
    size_t rowB = (size_t)(h + 8 + half * 16) * RT + t;   // head h+8 / h+24
    size_t xa = rowA * RD;
    size_t xb = rowB * RD;
    size_t cb = (size_t)t * RD;

    // ---- 8 front-batched 16B loads ----
    float4 xloA = __ldcs(reinterpret_cast<const float4*>(x + xa)      + ll);
    float4 xhiA = __ldcs(reinterpret_cast<const float4*>(x + xa + 64) + ll);
    float4 xloB = __ldcs(reinterpret_cast<const float4*>(x + xb)      + ll);
    float4 xhiB = __ldcs(reinterpret_cast<const float4*>(x + xb + 64) + ll);
    float4 clo  = *(reinterpret_cast<const float4*>(cosp + cb)      + ll);
    float4 chi  = *(reinterpret_cast<const float4*>(cosp + cb + 64) + ll);
    float4 slo  = *(reinterpret_cast<const float4*>(sinp + cb)      + ll);
    float4 shi  = *(reinterpret_cast<const float4*>(sinp + cb + 64) + ll);

    // ---- row A ----
    float4 oloA, ohiA;
    oloA.x = fmaf(-xhiA.x, slo.x, xloA.x * clo.x);
    oloA.y = fmaf(-xhiA.y, slo.y, xloA.y * clo.y);
    oloA.z = fmaf(-xhiA.z, slo.z, xloA.z * clo.z);
    oloA.w = fmaf(-xhiA.w, slo.w, xloA.w * clo.w);
    ohiA.x = fmaf( xloA.x, shi.x, xhiA.x * chi.x);
    ohiA.y = fmaf( xloA.y, shi.y, xhiA.y * chi.y);
    ohiA.z = fmaf( xloA.z, shi.z, xhiA.z * chi.z);
    ohiA.w = fmaf( xloA.w, shi.w, xhiA.w * chi.w);
    __stwt(reinterpret_cast<float4*>(out + xa)      + ll, oloA);
    __stwt(reinterpret_cast<float4*>(out + xa + 64) + ll, ohiA);

    // ---- row B ----
    float4 oloB, ohiB;
    oloB.x = fmaf(-xhiB.x, slo.x, xloB.x * clo.x);
    oloB.y = fmaf(-xhiB.y, slo.y, xloB.y * clo.y);
    oloB.z = fmaf(-xhiB.z, slo.z, xloB.z * clo.z);
    oloB.w = fmaf(-xhiB.w, slo.w, xloB.w * clo.w);
    ohiB.x = fmaf( xloB.x, shi.x, xhiB.x * chi.x);
    ohiB.y = fmaf( xloB.y, shi.y, xhiB.y * chi.y);
    ohiB.z = fmaf( xloB.z, shi.z, xhiB.z * chi.z);
    ohiB.w = fmaf( xloB.w, shi.w, xhiB.w * chi.w);
    __stwt(reinterpret_cast<float4*>(out + xb)      + ll, oloB);
    __stwt(reinterpret_cast<float4*>(out + xb + 64) + ll, ohiB);

    // ---- per-row max/min: butterflies over 16-lane halves ----
    float mxA = fmaxf(fmaxf(fmaxf(oloA.x, oloA.y), fmaxf(oloA.z, oloA.w)),
                      fmaxf(fmaxf(ohiA.x, ohiA.y), fmaxf(ohiA.z, ohiA.w)));
    float mnA = fminf(fminf(fminf(oloA.x, oloA.y), fminf(oloA.z, oloA.w)),
                      fminf(fminf(ohiA.x, ohiA.y), fminf(ohiA.z, ohiA.w)));
    float mxB = fmaxf(fmaxf(fmaxf(oloB.x, oloB.y), fmaxf(oloB.z, oloB.w)),
                      fmaxf(fmaxf(ohiB.x, ohiB.y), fmaxf(ohiB.z, ohiB.w)));
    float mnB = fminf(fminf(fminf(oloB.x, oloB.y), fminf(oloB.z, oloB.w)),
                      fminf(fminf(ohiB.x, ohiB.y), fminf(ohiB.z, ohiB.w)));
    #pragma unroll
    for (int off = 8; off > 0; off >>= 1) {
        mxA = fmaxf(mxA, __shfl_xor_sync(FULL, mxA, off));
        mnA = fminf(mnA, __shfl_xor_sync(FULL, mnA, off));
        mxB = fmaxf(mxB, __shfl_xor_sync(FULL, mxB, off));
        mnB = fminf(mnB, __shfl_xor_sync(FULL, mnB, off));
    }
    if (ll == 0) {
        omax[rowA] = mxA;
        omin[rowA] = mnA;
        omax[rowB] = mxB;
        omin[rowB] = mnB;
    }
}

extern "C" void kernel_launch(void* const* d_in, const int* in_sizes, int n_in,
                              void* d_out, int out_size)
{
    // inputs: 0=x, 1=scale_x (unused), 2=cos, 3=scale_cos (unused),
    //         4=sin, 5=scale_sin (unused)
    const float* x    = (const float*)d_in[0];
    const float* cosp = (const float*)d_in[2];
    const float* sinp = (const float*)d_in[4];

    float* out  = (float*)d_out;
    float* omax = out + (size_t)RH * RT * RD;
    float* omin = omax + (size_t)RH * RT;

    const int warps = (RH / 4) * RT;        // 65536 (4 rows per warp)
    const int warps_per_block = 8;          // 256 threads
    const int blocks = warps / warps_per_block;

    rope_kernel<<<blocks, warps_per_block * 32>>>(x, cosp, sinp, out, omax, omin);
}